// round 7
// baseline (speedup 1.0000x reference)
#include <cuda_runtime.h>
#include <cstdint>

#define T_TOK 2048
#define DDIM  2048
#define NOUT  11264
#define LEXP  16
#define HALF_B 5632

// ---------------- scratch (device globals: allocation-free) ----------------
// x and W rounded to tf32 (RN) AND column-permuted within each 8-float group:
// physical [l0,l4,l1,l5,l2,l6,l3,l7]  (so mma K-pairs (q, q+4) are adjacent)
__device__ __align__(16) float g_xr[(size_t)T_TOK * DDIM];
__device__ __align__(16) float g_wr[(size_t)NOUT * DDIM];
__device__ float g_xa[T_TOK * 32];                           // xa = x . A[l]
__device__ int   g_tok[T_TOK];                               // tokens sorted by expert
__device__ int   g_start[LEXP + 1];                          // expert segment starts

__device__ __forceinline__ float tf32_rn(float f) {
    uint32_t u;
    asm("cvt.rna.tf32.f32 %0, %1;" : "=r"(u) : "f"(f));
    return __uint_as_float(u);
}

// ------- kernel 1: round+permute x,W -> scratch; last block also sorts -------
__global__ __launch_bounds__(256) void round_sort_kernel(const float4* __restrict__ x,
                                                         const float4* __restrict__ W,
                                                         const void* idx_raw) {
    if (blockIdx.x == gridDim.x - 1) {
        // ---- token bucketing by expert (single block) ----
        __shared__ int cnt[LEXP];
        __shared__ int base[LEXP];
        __shared__ int is64;
        int tid = threadIdx.x;
        if (tid < LEXP) cnt[tid] = 0;
        if (tid == 0) is64 = 1;
        __syncthreads();

        const int* a32 = (const int*)idx_raw;
        for (int j = tid; j < 1024; j += blockDim.x)
            if (a32[2 * j + 1] != 0) is64 = 0;   // benign race
        __syncthreads();
        const long long* a64 = (const long long*)idx_raw;
        int use64 = is64;

        for (int t = tid; t < T_TOK; t += blockDim.x) {
            int l = use64 ? (int)a64[t] : a32[t];
            atomicAdd(&cnt[l], 1);
        }
        __syncthreads();
        if (tid == 0) {
            int s = 0;
            for (int l = 0; l < LEXP; ++l) { base[l] = s; g_start[l] = s; s += cnt[l]; }
            g_start[LEXP] = s;
        }
        __syncthreads();
        for (int t = tid; t < T_TOK; t += blockDim.x) {
            int l = use64 ? (int)a64[t] : a32[t];
            int p = atomicAdd(&base[l], 1);
            g_tok[p] = t;
        }
        for (int i = tid; i < T_TOK * 32; i += blockDim.x) g_xa[i] = 0.0f;
        return;
    }

    // ---- round + permute: one 8-float group per thread-step ----
    const size_t nx8 = (size_t)T_TOK * DDIM / 8;   // 8-float groups in x
    const size_t nw8 = (size_t)NOUT * DDIM / 8;
    float4* ox = (float4*)g_xr;
    float4* ow = (float4*)g_wr;
    size_t stride = (size_t)(gridDim.x - 1) * blockDim.x;
    for (size_t i = (size_t)blockIdx.x * blockDim.x + threadIdx.x; i < nx8 + nw8; i += stride) {
        float4 lo, hi;
        float4* dst;
        if (i < nx8) { lo = x[2 * i]; hi = x[2 * i + 1]; dst = ox + 2 * i; }
        else {
            size_t j = i - nx8;
            lo = W[2 * j]; hi = W[2 * j + 1]; dst = ow + 2 * j;
        }
        float4 p0, p1;   // interleave: [l0,l4,l1,l5] , [l2,l6,l3,l7]
        p0.x = tf32_rn(lo.x); p0.y = tf32_rn(hi.x);
        p0.z = tf32_rn(lo.y); p0.w = tf32_rn(hi.y);
        p1.x = tf32_rn(lo.z); p1.y = tf32_rn(hi.z);
        p1.z = tf32_rn(lo.w); p1.w = tf32_rn(hi.w);
        dst[0] = p0;
        dst[1] = p1;
    }
}

// ---------------- kernel 2: xa[t, j] = sum_d x[t,d] * A[l, d, j] ----------------
__global__ __launch_bounds__(512) void xa_kernel(const float* __restrict__ x,
                                                 const float* __restrict__ A) {
    __shared__ float As[128 * 32];
    int l = blockIdx.y;
    int d0 = blockIdx.x * 128;
    int tid = threadIdx.x;
    int lane = tid & 31, w = tid >> 5;

    size_t abase = ((size_t)l * DDIM + d0) * 32;
    for (int i = tid; i < 128 * 32; i += 512) As[i] = A[abase + i];
    __syncthreads();

    int pbeg = g_start[l], pend = g_start[l + 1];
    for (int p = pbeg + w; p < pend; p += 16) {
        int t = g_tok[p];
        float xv[4];
#pragma unroll
        for (int s = 0; s < 4; ++s)
            xv[s] = x[(size_t)t * DDIM + d0 + s * 32 + lane];
        float acc = 0.0f;
#pragma unroll
        for (int s = 0; s < 4; ++s) {
#pragma unroll
            for (int i = 0; i < 32; ++i) {
                float xb = __shfl_sync(0xffffffffu, xv[s], i);
                acc += xb * As[(s * 32 + i) * 32 + lane];
            }
        }
        atomicAdd(&g_xa[t * 32 + lane], acc);
    }
}

// ---------------- kernel 3: delta -> out (full init), B in registers ----------
__global__ __launch_bounds__(256) void delta_kernel(const float* __restrict__ B,
                                                    float* __restrict__ out) {
    int l = blockIdx.y;
    int n0 = blockIdx.x * 512;
    int half = (n0 >= HALF_B) ? 1 : 0;
    int tid = threadIdx.x;
    int c0 = n0 + 2 * tid;

    float2 Breg[16];
#pragma unroll
    for (int r = 0; r < 16; ++r)
        Breg[r] = *(const float2*)(B + ((size_t)l * 16 + r) * NOUT + c0);

    const float4* xa4base = (const float4*)(g_xa) + half * 4;

    int pbeg = g_start[l], pend = g_start[l + 1];
    for (int p = pbeg; p < pend; ++p) {
        int t = g_tok[p];
        float4 x0 = __ldg(xa4base + t * 8 + 0);
        float4 x1 = __ldg(xa4base + t * 8 + 1);
        float4 x2 = __ldg(xa4base + t * 8 + 2);
        float4 x3 = __ldg(xa4base + t * 8 + 3);
        float xs[16] = {x0.x, x0.y, x0.z, x0.w, x1.x, x1.y, x1.z, x1.w,
                        x2.x, x2.y, x2.z, x2.w, x3.x, x3.y, x3.z, x3.w};
        float2 acc = make_float2(0.0f, 0.0f);
#pragma unroll
        for (int r = 0; r < 16; ++r) {
            acc.x += xs[r] * Breg[r].x;
            acc.y += xs[r] * Breg[r].y;
        }
        *(float2*)(out + (size_t)t * NOUT + c0) = acc;
    }
}

// ---------------- kernel 4: main GEMM (tf32 mma.sync), out += x @ W.T --------
#define BM 128
#define BN 128
#define BK 32
#define PAD 36                         // smem row stride in floats
#define STAGES 3
#define STAGE_FLOATS ((BM + BN) * PAD) // 9216 floats = 36864 B per stage
#define SMEM_GEMM (STAGES * STAGE_FLOATS * 4)   // 110592 B

__device__ __forceinline__ void cpa16(uint32_t s, const void* g) {
    asm volatile("cp.async.cg.shared.global [%0], [%1], 16;\n" :: "r"(s), "l"(g));
}

__global__ __launch_bounds__(256, 2) void gemm_kernel(float* __restrict__ out) {
    extern __shared__ float smem[];

    int tid = threadIdx.x;
    int lane = tid & 31;
    int warp = tid >> 5;
    int warpM = warp & 3;    // 4 warps in M  -> 32 rows each
    int warpN = warp >> 2;   // 2 warps in N  -> 64 cols each
    int grp = lane >> 2;     // 0..7
    int qid = lane & 3;      // 0..3

    int bm = blockIdx.x;     // 0..15
    int bn = blockIdx.y;     // 0..87

    const float* gA = g_xr + (size_t)(bm * BM) * DDIM;
    const float* gB = g_wr + (size_t)(bn * BN) * DDIM;

    int rbase = tid >> 3;    // 0..31
    int seg = tid & 7;       // 0..7

    uint32_t sBase = (uint32_t)__cvta_generic_to_shared(smem);

    float c[2][8][4];
#pragma unroll
    for (int mt = 0; mt < 2; ++mt)
#pragma unroll
        for (int nt = 0; nt < 8; ++nt)
#pragma unroll
            for (int i = 0; i < 4; ++i) c[mt][nt][i] = 0.0f;

    auto loadTiles = [&](int buf, int k0) {
        uint32_t aoff = sBase + (uint32_t)(buf * STAGE_FLOATS) * 4u;
        uint32_t boff = aoff + (uint32_t)(BM * PAD) * 4u;
#pragma unroll
        for (int i = 0; i < 4; ++i) {
            int row = rbase + i * 32;
            cpa16(aoff + (uint32_t)(row * PAD + seg * 4) * 4u,
                  gA + (size_t)row * DDIM + k0 + seg * 4);
            cpa16(boff + (uint32_t)(row * PAD + seg * 4) * 4u,
                  gB + (size_t)row * DDIM + k0 + seg * 4);
        }
        asm volatile("cp.async.commit_group;\n");
    };

    loadTiles(0, 0);
    loadTiles(1, BK);

    const int NITER = DDIM / BK;   // 64
#pragma unroll 1
    for (int it = 0; it < NITER; ++it) {
        if (it < NITER - 1) {
            asm volatile("cp.async.wait_group 1;\n");
        } else {
            asm volatile("cp.async.wait_group 0;\n");
        }
        __syncthreads();
        if (it + 2 < NITER) {
            int nbuf = (it + 2) % STAGES;
            loadTiles(nbuf, (it + 2) * BK);
        }

        int buf = it % STAGES;
        const uint32_t* AsU = (const uint32_t*)(smem + buf * STAGE_FLOATS);
        const uint32_t* BsU = AsU + BM * PAD;
        int aRow = warpM * 32 + grp;
        int bRow = warpN * 64 + grp;

#pragma unroll
        for (int ks = 0; ks < 4; ++ks) {
            // permuted layout: logical K-pair (ks*8+qid, ks*8+qid+4)
            // lives at physical floats (ks*8 + 2*qid, +1)  -> one LDS.64
            int koff = ks * 8 + 2 * qid;
            uint32_t a[2][4], b[8][2];
#pragma unroll
            for (int mt = 0; mt < 2; ++mt) {
                uint2 lo = *(const uint2*)(AsU + (aRow + mt * 16) * PAD + koff);
                uint2 hi = *(const uint2*)(AsU + (aRow + mt * 16 + 8) * PAD + koff);
                a[mt][0] = lo.x;  // A[row,   k]
                a[mt][1] = hi.x;  // A[row+8, k]
                a[mt][2] = lo.y;  // A[row,   k+4]
                a[mt][3] = hi.y;  // A[row+8, k+4]
            }
#pragma unroll
            for (int nt = 0; nt < 8; ++nt) {
                uint2 v = *(const uint2*)(BsU + (bRow + nt * 8) * PAD + koff);
                b[nt][0] = v.x;
                b[nt][1] = v.y;
            }
#pragma unroll
            for (int mt = 0; mt < 2; ++mt) {
#pragma unroll
                for (int nt = 0; nt < 8; ++nt) {
                    asm volatile(
                        "mma.sync.aligned.m16n8k8.row.col.f32.tf32.tf32.f32 "
                        "{%0,%1,%2,%3}, {%4,%5,%6,%7}, {%8,%9}, {%0,%1,%2,%3};\n"
                        : "+f"(c[mt][nt][0]), "+f"(c[mt][nt][1]),
                          "+f"(c[mt][nt][2]), "+f"(c[mt][nt][3])
                        : "r"(a[mt][0]), "r"(a[mt][1]), "r"(a[mt][2]), "r"(a[mt][3]),
                          "r"(b[nt][0]), "r"(b[nt][1]));
                }
            }
        }
    }

    // epilogue: out += acc (out already holds delta)
#pragma unroll
    for (int mt = 0; mt < 2; ++mt) {
#pragma unroll
        for (int nt = 0; nt < 8; ++nt) {
            int r = bm * BM + warpM * 32 + mt * 16 + grp;
            int col = bn * BN + warpN * 64 + nt * 8 + qid * 2;
            size_t o = (size_t)r * NOUT + col;
            float2* p0 = (float2*)(out + o);
            float2 v0 = *p0;
            v0.x += c[mt][nt][0];
            v0.y += c[mt][nt][1];
            *p0 = v0;
            float2* p1 = (float2*)(out + o + (size_t)8 * NOUT);
            float2 v1 = *p1;
            v1.x += c[mt][nt][2];
            v1.y += c[mt][nt][3];
            *p1 = v1;
        }
    }
}

// ---------------- launch ----------------
extern "C" void kernel_launch(void* const* d_in, const int* in_sizes, int n_in,
                              void* d_out, int out_size) {
    const float* x = (const float*)d_in[0];
    const float* W = (const float*)d_in[1];
    const float* A = (const float*)d_in[2];
    const float* B = (const float*)d_in[3];
    const void*  idx = d_in[4];
    float* out = (float*)d_out;

    (void)in_sizes; (void)n_in; (void)out_size;

    cudaFuncSetAttribute(gemm_kernel, cudaFuncAttributeMaxDynamicSharedMemorySize, SMEM_GEMM);

    round_sort_kernel<<<2049, 256>>>((const float4*)x, (const float4*)W, idx);
    xa_kernel<<<dim3(16, 16), 512>>>(x, A);
    delta_kernel<<<dim3(22, 16), 256>>>(B, out);
    gemm_kernel<<<dim3(16, 88), 256, SMEM_GEMM>>>(out);
}

// round 8
// speedup vs baseline: 1.8574x; 1.8574x over previous
#include <cuda_runtime.h>
#include <cstdint>

#define T_TOK 2048
#define DDIM  2048
#define NOUT  11264
#define LEXP  16
#define HALF_B 5632

// ---------------- scratch (device globals: allocation-free) ----------------
__device__ __align__(16) float g_xr[(size_t)T_TOK * DDIM];   // tf32-rounded x
__device__ __align__(16) float g_wr[(size_t)NOUT * DDIM];    // tf32-rounded W
__device__ float g_xa[T_TOK * 32];                           // xa = x . A[l]
__device__ int   g_tok[T_TOK];                               // tokens sorted by expert
__device__ int   g_start[LEXP + 1];                          // expert segment starts

__device__ __forceinline__ float tf32_rn(float f) {
    uint32_t u;
    asm("cvt.rna.tf32.f32 %0, %1;" : "=r"(u) : "f"(f));
    return __uint_as_float(u);
}

// ---------------- kernel 1: bucket tokens by expert + zero xa ----------------
__global__ __launch_bounds__(1024) void sort_kernel(const void* idx_raw) {
    __shared__ int cnt[LEXP];
    __shared__ int base[LEXP];
    __shared__ int is64;
    int tid = threadIdx.x;
    if (tid < LEXP) cnt[tid] = 0;
    if (tid == 0) is64 = 1;
    __syncthreads();

    // sniff int32 vs int64: if int64 (values in [0,16)), every odd 32-bit word is 0
    const int* a32 = (const int*)idx_raw;
    for (int j = tid; j < 1024; j += blockDim.x)
        if (a32[2 * j + 1] != 0) is64 = 0;   // benign race
    __syncthreads();
    const long long* a64 = (const long long*)idx_raw;
    int use64 = is64;

    for (int t = tid; t < T_TOK; t += blockDim.x) {
        int l = use64 ? (int)a64[t] : a32[t];
        atomicAdd(&cnt[l], 1);
    }
    __syncthreads();
    if (tid == 0) {
        int s = 0;
        for (int l = 0; l < LEXP; ++l) { base[l] = s; g_start[l] = s; s += cnt[l]; }
        g_start[LEXP] = s;
    }
    __syncthreads();
    for (int t = tid; t < T_TOK; t += blockDim.x) {
        int l = use64 ? (int)a64[t] : a32[t];
        int p = atomicAdd(&base[l], 1);
        g_tok[p] = t;
    }
    for (int i = tid; i < T_TOK * 32; i += blockDim.x) g_xa[i] = 0.0f;
}

// ---------------- kernel 2: round x and W to tf32 (RN) ----------------
__global__ __launch_bounds__(256) void round_kernel(const float4* __restrict__ x,
                                                    const float4* __restrict__ W) {
    const size_t nx = (size_t)T_TOK * DDIM / 4;
    const size_t nw = (size_t)NOUT * DDIM / 4;
    float4* ox = (float4*)g_xr;
    float4* ow = (float4*)g_wr;
    size_t stride = (size_t)gridDim.x * blockDim.x;
    for (size_t i = (size_t)blockIdx.x * blockDim.x + threadIdx.x; i < nx + nw; i += stride) {
        float4 v;
        float4* dst;
        if (i < nx) { v = x[i]; dst = ox + i; }
        else        { v = W[i - nx]; dst = ow + (i - nx); }
        v.x = tf32_rn(v.x); v.y = tf32_rn(v.y);
        v.z = tf32_rn(v.z); v.w = tf32_rn(v.w);
        *dst = v;
    }
}

// ---------------- kernel 3: xa[t, j] = sum_d x[t,d] * A[l, d, j] ----------------
__global__ __launch_bounds__(512) void xa_kernel(const float* __restrict__ x,
                                                 const float* __restrict__ A) {
    __shared__ float As[128 * 32];
    int l = blockIdx.y;
    int d0 = blockIdx.x * 128;
    int tid = threadIdx.x;
    int lane = tid & 31, w = tid >> 5;

    size_t abase = ((size_t)l * DDIM + d0) * 32;
    for (int i = tid; i < 128 * 32; i += 512) As[i] = A[abase + i];
    __syncthreads();

    int pbeg = g_start[l], pend = g_start[l + 1];
    for (int p = pbeg + w; p < pend; p += 16) {
        int t = g_tok[p];
        float xv[4];
#pragma unroll
        for (int s = 0; s < 4; ++s)
            xv[s] = x[(size_t)t * DDIM + d0 + s * 32 + lane];
        float acc = 0.0f;
#pragma unroll
        for (int s = 0; s < 4; ++s) {
#pragma unroll
            for (int i = 0; i < 32; ++i) {
                float xb = __shfl_sync(0xffffffffu, xv[s], i);
                acc += xb * As[(s * 32 + i) * 32 + lane];
            }
        }
        atomicAdd(&g_xa[t * 32 + lane], acc);
    }
}

// ---------------- kernel 4: delta -> out (full init), B in regs, 4-way z-split
// grid (22 ntiles of 512 cols, 16 experts, 4 token-chunks), 256 threads.
__global__ __launch_bounds__(256) void delta_kernel(const float* __restrict__ B,
                                                    float* __restrict__ out) {
    int l = blockIdx.y;
    int n0 = blockIdx.x * 512;
    int half = (n0 >= HALF_B) ? 1 : 0;
    int tid = threadIdx.x;
    int c0 = n0 + 2 * tid;

    int pbeg = g_start[l], pend = g_start[l + 1];
    int len = pend - pbeg;
    int per = (len + 3) >> 2;
    int s = pbeg + blockIdx.z * per;
    int e = s + per;
    if (e > pend) e = pend;
    if (s >= e) return;

    // B tile for this (expert, col-pair): 16 float2 in registers
    float2 Breg[16];
#pragma unroll
    for (int r = 0; r < 16; ++r)
        Breg[r] = *(const float2*)(B + ((size_t)l * 16 + r) * NOUT + c0);

    const float4* xa4base = (const float4*)(g_xa) + half * 4;

    for (int p = s; p < e; ++p) {
        int t = g_tok[p];
        float4 x0 = __ldg(xa4base + t * 8 + 0);
        float4 x1 = __ldg(xa4base + t * 8 + 1);
        float4 x2 = __ldg(xa4base + t * 8 + 2);
        float4 x3 = __ldg(xa4base + t * 8 + 3);
        float xs[16] = {x0.x, x0.y, x0.z, x0.w, x1.x, x1.y, x1.z, x1.w,
                        x2.x, x2.y, x2.z, x2.w, x3.x, x3.y, x3.z, x3.w};
        float2 acc = make_float2(0.0f, 0.0f);
#pragma unroll
        for (int r = 0; r < 16; ++r) {
            acc.x += xs[r] * Breg[r].x;
            acc.y += xs[r] * Breg[r].y;
        }
        *(float2*)(out + (size_t)t * NOUT + c0) = acc;
    }
}

// ---------------- kernel 5: main GEMM (tf32 mma.sync), out += x @ W.T --------
#define BM 128
#define BN 128
#define BK 32
#define PAD 36                         // smem row stride in floats
#define STAGES 3
#define STAGE_FLOATS ((BM + BN) * PAD) // 9216 floats = 36864 B per stage
#define SMEM_GEMM (STAGES * STAGE_FLOATS * 4)   // 110592 B

__device__ __forceinline__ void cpa16(uint32_t s, const void* g) {
    asm volatile("cp.async.cg.shared.global [%0], [%1], 16;\n" :: "r"(s), "l"(g));
}

__global__ __launch_bounds__(256, 2) void gemm_kernel(float* __restrict__ out) {
    extern __shared__ float smem[];

    int tid = threadIdx.x;
    int lane = tid & 31;
    int warp = tid >> 5;
    int warpM = warp & 3;    // 4 warps in M  -> 32 rows each
    int warpN = warp >> 2;   // 2 warps in N  -> 64 cols each
    int grp = lane >> 2;     // 0..7
    int qid = lane & 3;      // 0..3

    int bm = blockIdx.x;     // 0..15
    int bn = blockIdx.y;     // 0..87

    const float* gA = g_xr + (size_t)(bm * BM) * DDIM;
    const float* gB = g_wr + (size_t)(bn * BN) * DDIM;

    int rbase = tid >> 3;    // 0..31
    int seg = tid & 7;       // 0..7

    uint32_t sBase = (uint32_t)__cvta_generic_to_shared(smem);

    float c[2][8][4];
#pragma unroll
    for (int mt = 0; mt < 2; ++mt)
#pragma unroll
        for (int nt = 0; nt < 8; ++nt)
#pragma unroll
            for (int i = 0; i < 4; ++i) c[mt][nt][i] = 0.0f;

    auto loadTiles = [&](int buf, int k0) {
        uint32_t aoff = sBase + (uint32_t)(buf * STAGE_FLOATS) * 4u;
        uint32_t boff = aoff + (uint32_t)(BM * PAD) * 4u;
#pragma unroll
        for (int i = 0; i < 4; ++i) {
            int row = rbase + i * 32;
            cpa16(aoff + (uint32_t)(row * PAD + seg * 4) * 4u,
                  gA + (size_t)row * DDIM + k0 + seg * 4);
            cpa16(boff + (uint32_t)(row * PAD + seg * 4) * 4u,
                  gB + (size_t)row * DDIM + k0 + seg * 4);
        }
        asm volatile("cp.async.commit_group;\n");
    };

    auto compute = [&](int buf) {
        const uint32_t* AsU = (const uint32_t*)(smem + buf * STAGE_FLOATS);
        const uint32_t* BsU = AsU + BM * PAD;
        int aRow = warpM * 32 + grp;
        int bRow = warpN * 64 + grp;
#pragma unroll
        for (int ks = 0; ks < 4; ++ks) {
            int kb = ks * 8 + qid;
            uint32_t a[2][4], b[8][2];
#pragma unroll
            for (int mt = 0; mt < 2; ++mt) {
                const uint32_t* p = AsU + (aRow + mt * 16) * PAD + kb;
                a[mt][0] = p[0];
                a[mt][1] = p[8 * PAD];
                a[mt][2] = p[4];
                a[mt][3] = p[8 * PAD + 4];
            }
#pragma unroll
            for (int nt = 0; nt < 8; ++nt) {
                const uint32_t* p = BsU + (bRow + nt * 8) * PAD + kb;
                b[nt][0] = p[0];
                b[nt][1] = p[4];
            }
#pragma unroll
            for (int mt = 0; mt < 2; ++mt) {
#pragma unroll
                for (int nt = 0; nt < 8; ++nt) {
                    asm volatile(
                        "mma.sync.aligned.m16n8k8.row.col.f32.tf32.tf32.f32 "
                        "{%0,%1,%2,%3}, {%4,%5,%6,%7}, {%8,%9}, {%0,%1,%2,%3};\n"
                        : "+f"(c[mt][nt][0]), "+f"(c[mt][nt][1]),
                          "+f"(c[mt][nt][2]), "+f"(c[mt][nt][3])
                        : "r"(a[mt][0]), "r"(a[mt][1]), "r"(a[mt][2]), "r"(a[mt][3]),
                          "r"(b[nt][0]), "r"(b[nt][1]));
                }
            }
        }
    };

    loadTiles(0, 0);
    loadTiles(1, BK);

    const int NITER = DDIM / BK;   // 64
    // Unrolled-by-3 steady state: stage offsets are compile-time constants,
    // eliminating per-iter buf/address integer math (alu was 22% of issue).
#pragma unroll 1
    for (int it = 0; it < NITER - 4; it += 3) {
#pragma unroll
        for (int u = 0; u < 3; ++u) {
            asm volatile("cp.async.wait_group 1;\n");
            __syncthreads();
            loadTiles((u + 2) % STAGES, (it + u + 2) * BK);
            compute(u);   // (it + u) % 3 == u since it % 3 == 0
        }
    }
    // tail: it = 60, 61, 62, 63  (60 % 3 == 0)
#pragma unroll
    for (int u = 0; u < 4; ++u) {
        int it = 60 + u;
        if (it < NITER - 1) {
            asm volatile("cp.async.wait_group 1;\n");
        } else {
            asm volatile("cp.async.wait_group 0;\n");
        }
        __syncthreads();
        if (it + 2 < NITER)
            loadTiles((u + 2) % STAGES, (it + 2) * BK);
        compute(u % STAGES);
    }

    // epilogue: out += acc (out already holds delta)
#pragma unroll
    for (int mt = 0; mt < 2; ++mt) {
#pragma unroll
        for (int nt = 0; nt < 8; ++nt) {
            int r = bm * BM + warpM * 32 + mt * 16 + grp;
            int col = bn * BN + warpN * 64 + nt * 8 + qid * 2;
            size_t o = (size_t)r * NOUT + col;
            float2* p0 = (float2*)(out + o);
            float2 v0 = *p0;
            v0.x += c[mt][nt][0];
            v0.y += c[mt][nt][1];
            *p0 = v0;
            float2* p1 = (float2*)(out + o + (size_t)8 * NOUT);
            float2 v1 = *p1;
            v1.x += c[mt][nt][2];
            v1.y += c[mt][nt][3];
            *p1 = v1;
        }
    }
}

// ---------------- launch ----------------
extern "C" void kernel_launch(void* const* d_in, const int* in_sizes, int n_in,
                              void* d_out, int out_size) {
    const float* x = (const float*)d_in[0];
    const float* W = (const float*)d_in[1];
    const float* A = (const float*)d_in[2];
    const float* B = (const float*)d_in[3];
    const void*  idx = d_in[4];
    float* out = (float*)d_out;

    (void)in_sizes; (void)n_in; (void)out_size;

    cudaFuncSetAttribute(gemm_kernel, cudaFuncAttributeMaxDynamicSharedMemorySize, SMEM_GEMM);

    sort_kernel<<<1, 1024>>>(idx);
    round_kernel<<<2048, 256>>>((const float4*)x, (const float4*)W);
    xa_kernel<<<dim3(16, 16), 512>>>(x, A);
    delta_kernel<<<dim3(22, 16, 4), 256>>>(B, out);
    gemm_kernel<<<dim3(16, 88), 256, SMEM_GEMM>>>(out);
}